// round 1
// baseline (speedup 1.0000x reference)
#include <cuda_runtime.h>
#include <cuda_bf16.h>

#define NX 1024
#define NY 1024
#define EPSV 1e-10f
#define PTS_PER_THREAD 16
#define BLOCK_T 256
#define PTS_PER_BLOCK (PTS_PER_THREAD * BLOCK_T)

// Scratch (allocation-free rule: __device__ globals)
__device__ float  g_gx[NX];
__device__ float  g_gy[NY];
// Packed 2x2 stencil: g_quad[ix*1024 + iy] = {u00, u10, u01, u11}, ix in [0,1022], iy in [0,1022]
__device__ float4 g_quad[(NX - 1) * NY];

// ---------------------------------------------------------------------------
// Kernel 1: build adaptive grids. block 0 -> x grid, block 1 -> y grid.
// softplus -> clamp(1e-6) -> inclusive scan -> normalize; grid[0]=0, grid[N-1]=1.
// ---------------------------------------------------------------------------
__global__ void build_grids(const float* __restrict__ incx,
                            const float* __restrict__ incy) {
    __shared__ float s[1024];
    const float* inc = (blockIdx.x == 0) ? incx : incy;
    float* g         = (blockIdx.x == 0) ? g_gx : g_gy;

    int t = threadIdx.x;
    float v = 0.0f;
    if (t < 1023) {
        float xv = inc[t];
        // numerically-stable softplus matching jax.nn.softplus
        float sp = fmaxf(xv, 0.0f) + log1pf(expf(-fabsf(xv)));
        v = fmaxf(sp, 1e-6f);
    }
    s[t] = v;
    __syncthreads();

    // Hillis-Steele inclusive scan over 1024 slots (tail slot is 0, harmless)
    #pragma unroll
    for (int off = 1; off < 1024; off <<= 1) {
        float add = (t >= off) ? s[t - off] : 0.0f;
        __syncthreads();
        s[t] += add;
        __syncthreads();
    }

    float total = s[1022];  // cum[-1]
    if (t == 0) g[0] = 0.0f;
    if (t < 1023) {
        g[t + 1] = (t == 1022) ? 1.0f : s[t] / total;
    }
}

// ---------------------------------------------------------------------------
// Kernel 2: pack the 2x2 interpolation stencil into float4 (one 16B gather
// per eval point instead of 4 scalar gathers ~ 2.25 sectors).
// ---------------------------------------------------------------------------
__global__ void build_quad(const float* __restrict__ u) {
    int iy = blockIdx.x * blockDim.x + threadIdx.x;  // 0..1023
    int ix = blockIdx.y;                             // 0..1022
    if (iy > NY - 2) return;
    const float* r0 = u + ix * NY;
    const float* r1 = r0 + NY;
    float4 q;
    q.x = r0[iy];       // u00
    q.y = r1[iy];       // u10
    q.z = r0[iy + 1];   // u01
    q.w = r1[iy + 1];   // u11
    g_quad[(ix << 10) + iy] = q;
}

// ---------------------------------------------------------------------------
// Kernel 3: evaluate. Grids in smem; near-uniform-grid guess + O(1) fixup
// replaces binary search; single float4 L2 gather per point.
// ---------------------------------------------------------------------------
__global__ __launch_bounds__(BLOCK_T)
void eval_kernel(const float2* __restrict__ xe, float* __restrict__ out, int n) {
    __shared__ float sgx[NX];
    __shared__ float sgy[NY];
    for (int i = threadIdx.x; i < NX; i += BLOCK_T) sgx[i] = g_gx[i];
    for (int i = threadIdx.x; i < NY; i += BLOCK_T) sgy[i] = g_gy[i];
    __syncthreads();

    int base = blockIdx.x * PTS_PER_BLOCK;

    #pragma unroll 4
    for (int k = 0; k < PTS_PER_THREAD; k++) {
        int i = base + k * BLOCK_T + threadIdx.x;
        if (i >= n) break;

        float2 p = xe[i];
        float x = p.x, y = p.y;

        // searchsorted('left') - 1, clipped to [0, 1022]:
        // largest ix with grid[ix] < x (clamped).
        int ix = min(max(__float2int_rd(x * 1023.0f), 0), NX - 2);
        while (ix > 0 && sgx[ix] >= x) --ix;
        while (ix < NX - 2 && sgx[ix + 1] < x) ++ix;

        int iy = min(max(__float2int_rd(y * 1023.0f), 0), NY - 2);
        while (iy > 0 && sgy[iy] >= y) --iy;
        while (iy < NY - 2 && sgy[iy + 1] < y) ++iy;

        float xi  = sgx[ix], xi1 = sgx[ix + 1];
        float yi  = sgy[iy], yi1 = sgy[iy + 1];

        float4 q = __ldg(&g_quad[(ix << 10) + iy]);

        float rdx = 1.0f / fmaxf(xi1 - xi, EPSV);
        float rdy = 1.0f / fmaxf(yi1 - yi, EPSV);
        float n1x = (xi1 - x) * rdx;
        float n2x = (x - xi) * rdx;
        float n1y = (yi1 - y) * rdy;
        float n2y = (y - yi) * rdy;

        out[i] = n1y * (n1x * q.x + n2x * q.y) + n2y * (n1x * q.z + n2x * q.w);
    }
}

// ---------------------------------------------------------------------------
extern "C" void kernel_launch(void* const* d_in, const int* in_sizes, int n_in,
                              void* d_out, int out_size) {
    const float2* xe  = (const float2*)d_in[0];   // x_eval (N,2) f32
    const float* incx = (const float*)d_in[1];    // increments_x (1023)
    const float* incy = (const float*)d_in[2];    // increments_y (1023)
    const float* u    = (const float*)d_in[3];    // u (1024,1024)
    float* out        = (float*)d_out;
    int n = out_size;                             // 8,000,000

    build_grids<<<2, 1024>>>(incx, incy);

    dim3 qgrid((NY + 255) / 256, NX - 1);
    build_quad<<<qgrid, 256>>>(u);

    int blocks = (n + PTS_PER_BLOCK - 1) / PTS_PER_BLOCK;
    eval_kernel<<<blocks, BLOCK_T>>>(xe, out, n);
}